// round 7
// baseline (speedup 1.0000x reference)
#include <cuda_runtime.h>
#include <math.h>
#include <cstdint>

// Real spherical harmonics Y_{l,m}, l_max = 8, output [N, 81] fp32.
// Store-bound. Per-thread compute into smem in OUTPUT order (stride 81 is
// coprime with 32 banks -> conflict-free STS). Warp-local staging + flush
// (no block barrier). Flush uses 256-bit stores (st.global.cs.v8.f32,
// sm_100+) to halve STG instruction count.

namespace {
constexpr int LMAX  = 8;
constexpr int NCOLS = (LMAX + 1) * (LMAX + 1);  // 81
constexpr int BLK   = 128;
constexpr int WPTS  = 32;                        // points per warp
constexpr int WSPAN = WPTS * NCOLS;              // 2592 floats
constexpr int W8    = WSPAN / 8;                 // 324 v8-chunks

struct KTab { float v[LMAX + 1][LMAX + 1]; };

constexpr double cfact(int n) {
    double r = 1.0;
    for (int i = 2; i <= n; ++i) r *= (double)i;
    return r;
}
constexpr double csqrtd(double x) {
    double g = (x > 1.0) ? x : 1.0;
    for (int i = 0; i < 64; ++i) g = 0.5 * (g + x / g);
    return g;
}
constexpr double CPI = 3.14159265358979323846264338327950288;

constexpr KTab makeK() {
    KTab t{};
    for (int l = 0; l <= LMAX; ++l) {
        for (int m = 0; m <= l; ++m) {
            double k = csqrtd(((2.0 * l + 1.0) / (4.0 * CPI)) *
                              (cfact(l - m) / cfact(l + m)));
            if (m > 0) k *= csqrtd(2.0);
            t.v[l][m] = (float)k;
        }
    }
    return t;
}
}  // namespace

__constant__ KTab KT = makeK();

__device__ __forceinline__ void stg256_cs(float* p, float4 a, float4 b) {
    asm volatile(
        "st.global.cs.v8.f32 [%0], {%1,%2,%3,%4,%5,%6,%7,%8};"
        :: "l"(p),
           "f"(a.x), "f"(a.y), "f"(a.z), "f"(a.w),
           "f"(b.x), "f"(b.y), "f"(b.z), "f"(b.w)
        : "memory");
}

__global__ void __launch_bounds__(BLK)
sh_kernel(const float* __restrict__ ct_in,
          const float* __restrict__ ph_in,
          float* __restrict__ out, int n)
{
    __shared__ __align__(32) float s[BLK * NCOLS];  // 41472 B, output order

    const int t    = threadIdx.x;
    const int w    = t >> 5;
    const int lane = t & 31;
    const int base = blockIdx.x * BLK;
    const int i    = base + t;

    float ct = 0.0f, ph = 0.0f;
    if (i < n) { ct = ct_in[i]; ph = ph_in[i]; }

    float st = sqrtf(fmaxf(1.0f - ct * ct, 0.0f));
    float sp, cp;
    __sincosf(ph, &sp, &cp);

    float* row = s + t * NCOLS;

    float cm  = 1.0f;  // cos(m*phi)
    float smv = 0.0f;  // sin(m*phi)
    float pmm = 1.0f;  // P(m,m)

#pragma unroll
    for (int m = 0; m <= LMAX; ++m) {
        if (m > 0) {
            float c2 = cm * cp - smv * sp;
            float s2 = smv * cp + cm * sp;
            cm = c2; smv = s2;
            pmm *= st * (float)(2 * m - 1);   // P(m,m)
        }

        float Pa = pmm;  // l = m
        {
            const float k = KT.v[m][m];
            const int c0 = m * m + m;
            if (m == 0) {
                row[c0] = k * Pa;
            } else {
                float kp = k * Pa;
                row[c0 + m] = kp * cm;
                row[c0 - m] = kp * smv;
            }
        }

        if (m < LMAX) {
            float Pb = ct * (float)(2 * m + 1) * Pa;  // l = m+1
            {
                const int l  = m + 1;
                const float k = KT.v[l][m];
                const int c0 = l * l + l;
                if (m == 0) {
                    row[c0] = k * Pb;
                } else {
                    float kp = k * Pb;
                    row[c0 + m] = kp * cm;
                    row[c0 - m] = kp * smv;
                }
            }
#pragma unroll
            for (int l = m + 2; l <= LMAX; ++l) {
                float Pc = ((float)(2 * l - 1) * ct * Pb -
                            (float)(l + m - 1) * Pa) * (1.0f / (float)(l - m));
                const float k = KT.v[l][m];
                const int c0 = l * l + l;
                if (m == 0) {
                    row[c0] = k * Pc;
                } else {
                    float kp = k * Pc;
                    row[c0 + m] = kp * cm;
                    row[c0 - m] = kp * smv;
                }
                Pa = Pb; Pb = Pc;
            }
        }
    }

    __syncwarp();

    // Per-warp flush: this warp's span is contiguous in smem and gmem.
    const int wbase = base + w * WPTS;
    int npts = n - wbase;
    if (npts > WPTS) npts = WPTS;

    float* dst = out + (size_t)wbase * NCOLS;
    const float* ws = s + (size_t)w * WSPAN;

    if (npts == WPTS) {
        const float4* s4 = reinterpret_cast<const float4*>(ws);
        // 324 v8-chunks / 32 lanes = 10 full rounds + 4-lane tail
#pragma unroll 5
        for (int q = lane; q < W8; q += 32) {
            float4 a = s4[2 * q];
            float4 b = s4[2 * q + 1];
            stg256_cs(dst + 8 * q, a, b);
        }
    } else if (npts > 0) {
        int total = npts * NCOLS;
        for (int f = lane; f < total; f += 32) {
            __stcs(dst + f, ws[f]);
        }
    }
}

extern "C" void kernel_launch(void* const* d_in, const int* in_sizes, int n_in,
                              void* d_out, int out_size)
{
    int ia = (n_in >= 3) ? 1 : 0;
    const float* ct = (const float*)d_in[ia];
    const float* ph = (const float*)d_in[ia + 1];

    int n = out_size / NCOLS;
    if (n <= 0) return;

    int grid = (n + BLK - 1) / BLK;
    sh_kernel<<<grid, BLK>>>(ct, ph, (float*)d_out, n);
}

// round 8
// speedup vs baseline: 1.0854x; 1.0854x over previous
#include <cuda_runtime.h>
#include <math.h>

// Real spherical harmonics Y_{l,m}, l_max = 8, output [N, 81] fp32.
// Store-bound. Per-thread compute into smem in OUTPUT order (stride 81 is
// coprime with 32 banks -> conflict-free STS), block sync, then flush the
// contiguous block region with fully-unrolled coalesced float4 streaming
// stores (2592 = 20*128 + 32: 20 predicate-free rounds + 32-lane tail).

namespace {
constexpr int LMAX  = 8;
constexpr int NCOLS = (LMAX + 1) * (LMAX + 1);  // 81
constexpr int BLK   = 128;
constexpr int NQ    = (BLK * NCOLS) / 4;        // 2592 float4 per block

struct KTab { float v[LMAX + 1][LMAX + 1]; };

constexpr double cfact(int n) {
    double r = 1.0;
    for (int i = 2; i <= n; ++i) r *= (double)i;
    return r;
}
constexpr double csqrtd(double x) {
    double g = (x > 1.0) ? x : 1.0;
    for (int i = 0; i < 64; ++i) g = 0.5 * (g + x / g);
    return g;
}
constexpr double CPI = 3.14159265358979323846264338327950288;

constexpr KTab makeK() {
    KTab t{};
    for (int l = 0; l <= LMAX; ++l) {
        for (int m = 0; m <= l; ++m) {
            double k = csqrtd(((2.0 * l + 1.0) / (4.0 * CPI)) *
                              (cfact(l - m) / cfact(l + m)));
            if (m > 0) k *= csqrtd(2.0);
            t.v[l][m] = (float)k;
        }
    }
    return t;
}
}  // namespace

__constant__ KTab KT = makeK();

__global__ void __launch_bounds__(BLK)
sh_kernel(const float* __restrict__ ct_in,
          const float* __restrict__ ph_in,
          float* __restrict__ out, int n)
{
    __shared__ __align__(16) float s[BLK * NCOLS];  // 41472 B, output order

    const int t    = threadIdx.x;
    const int base = blockIdx.x * BLK;
    const int i    = base + t;

    float ct = 0.0f, ph = 0.0f;
    if (i < n) { ct = ct_in[i]; ph = ph_in[i]; }

    float st = sqrtf(fmaxf(1.0f - ct * ct, 0.0f));
    float sp, cp;
    __sincosf(ph, &sp, &cp);

    float* row = s + t * NCOLS;

    float cm  = 1.0f;  // cos(m*phi)
    float smv = 0.0f;  // sin(m*phi)
    float pmm = 1.0f;  // P(m,m)

#pragma unroll
    for (int m = 0; m <= LMAX; ++m) {
        if (m > 0) {
            float c2 = cm * cp - smv * sp;
            float s2 = smv * cp + cm * sp;
            cm = c2; smv = s2;
            pmm *= st * (float)(2 * m - 1);   // P(m,m)
        }

        float Pa = pmm;  // l = m
        {
            const float k = KT.v[m][m];
            const int c0 = m * m + m;
            if (m == 0) {
                row[c0] = k * Pa;
            } else {
                float kp = k * Pa;
                row[c0 + m] = kp * cm;
                row[c0 - m] = kp * smv;
            }
        }

        if (m < LMAX) {
            float Pb = ct * (float)(2 * m + 1) * Pa;  // l = m+1
            {
                const int l  = m + 1;
                const float k = KT.v[l][m];
                const int c0 = l * l + l;
                if (m == 0) {
                    row[c0] = k * Pb;
                } else {
                    float kp = k * Pb;
                    row[c0 + m] = kp * cm;
                    row[c0 - m] = kp * smv;
                }
            }
#pragma unroll
            for (int l = m + 2; l <= LMAX; ++l) {
                float Pc = ((float)(2 * l - 1) * ct * Pb -
                            (float)(l + m - 1) * Pa) * (1.0f / (float)(l - m));
                const float k = KT.v[l][m];
                const int c0 = l * l + l;
                if (m == 0) {
                    row[c0] = k * Pc;
                } else {
                    float kp = k * Pc;
                    row[c0 + m] = kp * cm;
                    row[c0 - m] = kp * smv;
                }
                Pa = Pb; Pb = Pc;
            }
        }
    }

    __syncthreads();

    float* dst = out + (size_t)base * NCOLS;
    int npts = n - base;
    if (npts > BLK) npts = BLK;

    if (npts == BLK) {
        const float4* s4 = reinterpret_cast<const float4*>(s);
        float4* d4 = reinterpret_cast<float4*>(dst);
        int q = t;
#pragma unroll
        for (int r = 0; r < NQ / BLK; ++r) {   // 20 predicate-free rounds
            __stcs(d4 + q, s4[q]);
            q += BLK;
        }
        if (t < NQ - (NQ / BLK) * BLK) {       // 32-lane tail (q = t + 2560)
            __stcs(d4 + q, s4[q]);
        }
    } else if (npts > 0) {
        int total = npts * NCOLS;
        for (int f = t; f < total; f += BLK) {
            __stcs(dst + f, s[f]);
        }
    }
}

extern "C" void kernel_launch(void* const* d_in, const int* in_sizes, int n_in,
                              void* d_out, int out_size)
{
    int ia = (n_in >= 3) ? 1 : 0;
    const float* ct = (const float*)d_in[ia];
    const float* ph = (const float*)d_in[ia + 1];

    int n = out_size / NCOLS;
    if (n <= 0) return;

    int grid = (n + BLK - 1) / BLK;
    sh_kernel<<<grid, BLK>>>(ct, ph, (float*)d_out, n);
}

// round 9
// speedup vs baseline: 1.1114x; 1.0240x over previous
#include <cuda_runtime.h>
#include <math.h>

// Real spherical harmonics Y_{l,m}, l_max = 8, output [N, 81] fp32.
// CHAMPION SHAPE (92.2us): store-bound; per-thread compute into smem in
// OUTPUT order (stride 81 coprime with 32 banks -> conflict-free STS),
// __syncthreads, then rolled (#pragma unroll 4) coalesced float4 streaming
// flush. Keeps regs ~48, 5 CTAs/SM. Measured 7.2 TB/s effective (~90% of
// HBM spec) — at the write-stream roofline.

namespace {
constexpr int LMAX  = 8;
constexpr int NCOLS = (LMAX + 1) * (LMAX + 1);  // 81
constexpr int BLK   = 128;
constexpr int NQ    = (BLK * NCOLS) / 4;        // 2592 float4 per block

struct KTab { float v[LMAX + 1][LMAX + 1]; };

constexpr double cfact(int n) {
    double r = 1.0;
    for (int i = 2; i <= n; ++i) r *= (double)i;
    return r;
}
constexpr double csqrtd(double x) {
    double g = (x > 1.0) ? x : 1.0;
    for (int i = 0; i < 64; ++i) g = 0.5 * (g + x / g);
    return g;
}
constexpr double CPI = 3.14159265358979323846264338327950288;

constexpr KTab makeK() {
    KTab t{};
    for (int l = 0; l <= LMAX; ++l) {
        for (int m = 0; m <= l; ++m) {
            double k = csqrtd(((2.0 * l + 1.0) / (4.0 * CPI)) *
                              (cfact(l - m) / cfact(l + m)));
            if (m > 0) k *= csqrtd(2.0);  // fold sqrt(2) for m != 0
            t.v[l][m] = (float)k;
        }
    }
    return t;
}
}  // namespace

__constant__ KTab KT = makeK();

__global__ void __launch_bounds__(BLK)
sh_kernel(const float* __restrict__ ct_in,
          const float* __restrict__ ph_in,
          float* __restrict__ out, int n)
{
    __shared__ __align__(16) float s[BLK * NCOLS];  // 41472 B, output order

    const int t    = threadIdx.x;
    const int base = blockIdx.x * BLK;
    const int i    = base + t;

    float ct = 0.0f, ph = 0.0f;
    if (i < n) { ct = ct_in[i]; ph = ph_in[i]; }

    float st = sqrtf(fmaxf(1.0f - ct * ct, 0.0f));
    float sp, cp;
    __sincosf(ph, &sp, &cp);

    float* row = s + t * NCOLS;

    float cm  = 1.0f;  // cos(m*phi)
    float smv = 0.0f;  // sin(m*phi)
    float pmm = 1.0f;  // P(m,m)

#pragma unroll
    for (int m = 0; m <= LMAX; ++m) {
        if (m > 0) {
            float c2 = cm * cp - smv * sp;
            float s2 = smv * cp + cm * sp;
            cm = c2; smv = s2;
            pmm *= st * (float)(2 * m - 1);   // P(m,m)
        }

        float Pa = pmm;  // l = m
        {
            const float k = KT.v[m][m];
            const int c0 = m * m + m;
            if (m == 0) {
                row[c0] = k * Pa;
            } else {
                float kp = k * Pa;
                row[c0 + m] = kp * cm;
                row[c0 - m] = kp * smv;
            }
        }

        if (m < LMAX) {
            float Pb = ct * (float)(2 * m + 1) * Pa;  // l = m+1
            {
                const int l  = m + 1;
                const float k = KT.v[l][m];
                const int c0 = l * l + l;
                if (m == 0) {
                    row[c0] = k * Pb;
                } else {
                    float kp = k * Pb;
                    row[c0 + m] = kp * cm;
                    row[c0 - m] = kp * smv;
                }
            }
#pragma unroll
            for (int l = m + 2; l <= LMAX; ++l) {
                float Pc = ((float)(2 * l - 1) * ct * Pb -
                            (float)(l + m - 1) * Pa) * (1.0f / (float)(l - m));
                const float k = KT.v[l][m];
                const int c0 = l * l + l;
                if (m == 0) {
                    row[c0] = k * Pc;
                } else {
                    float kp = k * Pc;
                    row[c0 + m] = kp * cm;
                    row[c0 - m] = kp * smv;
                }
                Pa = Pb; Pb = Pc;
            }
        }
    }

    __syncthreads();

    // Flush: block's region is contiguous in gmem AND in smem.
    float* dst = out + (size_t)base * NCOLS;
    int npts = n - base;
    if (npts > BLK) npts = BLK;

    if (npts == BLK) {
        const float4* s4 = reinterpret_cast<const float4*>(s);
        float4* d4 = reinterpret_cast<float4*>(dst);
#pragma unroll 4
        for (int q = t; q < NQ; q += BLK) {
            __stcs(d4 + q, s4[q]);   // streaming: write-once, no L2 pollution
        }
    } else if (npts > 0) {
        int total = npts * NCOLS;
        for (int f = t; f < total; f += BLK) {
            __stcs(dst + f, s[f]);
        }
    }
}

extern "C" void kernel_launch(void* const* d_in, const int* in_sizes, int n_in,
                              void* d_out, int out_size)
{
    int ia = (n_in >= 3) ? 1 : 0;
    const float* ct = (const float*)d_in[ia];
    const float* ph = (const float*)d_in[ia + 1];

    int n = out_size / NCOLS;
    if (n <= 0) return;

    int grid = (n + BLK - 1) / BLK;
    sh_kernel<<<grid, BLK>>>(ct, ph, (float*)d_out, n);
}